// round 8
// baseline (speedup 1.0000x reference)
#include <cuda_runtime.h>
#include <cuda_fp16.h>
#include <math.h>

// ---------------------------------------------------------------------------
// GNN_11957188952096: pre-linear -> SAGE(32->64) -> SAGE(64->64) -> pool -> MLP
// N=100000 nodes, E=1600000 edges, G=512 graphs
// CSR-by-dst gather aggregation; fp16 neighbor gather, fp32 accumulate
// ---------------------------------------------------------------------------

#define MAXN 100000
#define MAXE 1600000
#define MAXG 512
#define SCAN_B 1024

__device__ float g_h0[MAXN * 32];      // pre-linear output (fp32, root path)
__device__ __half2 g_h0h[MAXN * 16];   // fp16 copy for gather
__device__ float g_h1[MAXN * 64];      // conv1 output (fp32, root path)
__device__ __half2 g_h1h[MAXN * 32];   // fp16 copy for gather
__device__ float g_agg32[MAXN * 32];   // conv1 neighbor means
__device__ float g_agg64[MAXN * 64];   // conv2 neighbor means
__device__ float g_gsum[MAXG * 64];    // pooled sums
__device__ float g_gcnt[MAXG];         // nodes per graph

__device__ int g_deg[MAXN];
__device__ int g_scan[MAXN];
__device__ int g_rowptr[MAXN];
__device__ int g_fill[MAXN];
__device__ int g_adj[MAXE];
__device__ int g_bsum[256];
__device__ int g_boff[256];

typedef unsigned long long ull;

__device__ __forceinline__ void red_add_f32(float* addr, float v) {
    asm volatile("red.global.add.f32 [%0], %1;"
                 :: "l"(addr), "f"(v) : "memory");
}
__device__ __forceinline__ ull ffma2(ull a, ull b, ull c) {
    ull d;
    asm("fma.rn.f32x2 %0, %1, %2, %3;" : "=l"(d) : "l"(a), "l"(b), "l"(c));
    return d;
}
__device__ __forceinline__ ull dup2(float x) {
    ull d;
    asm("mov.b64 %0, {%1, %1};" : "=l"(d) : "r"(__float_as_uint(x)));
    return d;
}
__device__ __forceinline__ float2 unpack2(ull v) {
    float2 r;
    asm("mov.b64 {%0, %1}, %2;" : "=f"(r.x), "=f"(r.y) : "l"(v));
    return r;
}

// ---------------------------------------------------------------------------
__global__ void zero_small(int N) {
    int i = blockIdx.x * blockDim.x + threadIdx.x;
    int stride = gridDim.x * blockDim.x;
    for (int k = i; k < N; k += stride) g_deg[k] = 0;
    for (int k = i; k < MAXG * 64; k += stride) g_gsum[k] = 0.f;
    for (int k = i; k < MAXG; k += stride) g_gcnt[k] = 0.f;
}

// h0 = relu(x @ pre_w + pre_b); also emit fp16 copy
__global__ void pre_kernel(const float* __restrict__ x,
                           const float* __restrict__ w,
                           const float* __restrict__ b, int N) {
    __shared__ float sw[5 * 32];
    __shared__ float sb[32];
    for (int i = threadIdx.x; i < 160; i += blockDim.x) sw[i] = w[i];
    if (threadIdx.x < 32) sb[threadIdx.x] = b[threadIdx.x];
    __syncthreads();
    int n = blockIdx.x * blockDim.x + threadIdx.x;
    if (n >= N) return;
    float xv[5];
#pragma unroll
    for (int k = 0; k < 5; k++) xv[k] = x[n * 5 + k];
    float o[32];
#pragma unroll
    for (int j = 0; j < 32; j++) {
        float acc = sb[j];
#pragma unroll
        for (int k = 0; k < 5; k++) acc = fmaf(xv[k], sw[k * 32 + j], acc);
        o[j] = fmaxf(acc, 0.f);
        g_h0[n * 32 + j] = o[j];
    }
#pragma unroll
    for (int j = 0; j < 16; j++)
        g_h0h[n * 16 + j] = __floats2half2_rn(o[2 * j], o[2 * j + 1]);
}

// ---------------------------------------------------------------------------
// CSR construction
__global__ void hist_kernel(const int* __restrict__ dst, int E) {
    int e = blockIdx.x * blockDim.x + threadIdx.x;
    if (e < E) atomicAdd(&g_deg[dst[e]], 1);
}

__global__ void scan_s1(int N) {
    __shared__ int buf0[SCAN_B], buf1[SCAN_B];
    int t = threadIdx.x;
    int g = blockIdx.x * SCAN_B + t;
    buf0[t] = (g < N) ? g_deg[g] : 0;
    int* a = buf0; int* b = buf1;
#pragma unroll
    for (int off = 1; off < SCAN_B; off <<= 1) {
        __syncthreads();
        b[t] = (t >= off) ? a[t] + a[t - off] : a[t];
        int* tmp = a; a = b; b = tmp;
    }
    __syncthreads();
    if (g < N) g_scan[g] = a[t];
    if (t == SCAN_B - 1) g_bsum[blockIdx.x] = a[t];
}

// exclusive scan over <=128 block sums (own value captured before scan)
__global__ void scan_s2(int nb) {
    __shared__ int s0[128], s1[128];
    int t = threadIdx.x;
    int v = (t < nb) ? g_bsum[t] : 0;
    s0[t] = v;
    int* a = s0; int* b = s1;
#pragma unroll
    for (int off = 1; off < 128; off <<= 1) {
        __syncthreads();
        b[t] = (t >= off) ? a[t] + a[t - off] : a[t];
        int* tmp = a; a = b; b = tmp;
    }
    __syncthreads();
    if (t < nb) g_boff[t] = a[t] - v;   // exclusive prefix
}

__global__ void scan_s3(int N) {
    int g = blockIdx.x * SCAN_B + threadIdx.x;
    if (g < N) {
        g_rowptr[g] = g_scan[g] - g_deg[g] + g_boff[blockIdx.x];
        g_fill[g] = 0;
    }
}

__global__ void place_kernel(const int* __restrict__ src, const int* __restrict__ dst,
                             int E) {
    int e = blockIdx.x * blockDim.x + threadIdx.x;
    if (e >= E) return;
    int d = dst[e];
    int pos = g_rowptr[d] + atomicAdd(&g_fill[d], 1);
    g_adj[pos] = src[e];
}

// ---------------------------------------------------------------------------
// gather agg conv1 (fp16): 4 lanes x uint4(8 halves) per node, 8 nodes/warp
__global__ void agg1(int N) {
    int gw = (blockIdx.x * blockDim.x + threadIdx.x) >> 5;
    int lane = threadIdx.x & 31;
    int sub = lane >> 2, sl = lane & 3;
    int n = gw * 8 + sub;
    if (n >= N) return;
    int start = g_rowptr[n];
    int deg = g_deg[n];
    const uint4* h = (const uint4*)g_h0h;   // node row = 4 x uint4
    float acc[8];
#pragma unroll
    for (int j = 0; j < 8; j++) acc[j] = 0.f;
    for (int k = 0; k < deg; k++) {
        int s = __ldg(&g_adj[start + k]);
        uint4 v = h[s * 4 + sl];
        float2 f;
        f = __half22float2(*(__half2*)&v.x); acc[0] += f.x; acc[1] += f.y;
        f = __half22float2(*(((__half2*)&v.x) + 1)); acc[2] += f.x; acc[3] += f.y;
        f = __half22float2(*(__half2*)&v.z); acc[4] += f.x; acc[5] += f.y;
        f = __half22float2(*(((__half2*)&v.z) + 1)); acc[6] += f.x; acc[7] += f.y;
    }
    float inv = deg > 0 ? 1.f / (float)deg : 0.f;
    float4* out = (float4*)&g_agg32[n * 32 + sl * 8];
    out[0] = make_float4(acc[0] * inv, acc[1] * inv, acc[2] * inv, acc[3] * inv);
    out[1] = make_float4(acc[4] * inv, acc[5] * inv, acc[6] * inv, acc[7] * inv);
}

// gather agg conv2 (fp16): 8 lanes x uint4(8 halves) per node, 4 nodes/warp
__global__ void agg2(int N) {
    int gw = (blockIdx.x * blockDim.x + threadIdx.x) >> 5;
    int lane = threadIdx.x & 31;
    int sub = lane >> 3, sl = lane & 7;
    int n = gw * 4 + sub;
    if (n >= N) return;
    int start = g_rowptr[n];
    int deg = g_deg[n];
    const uint4* h = (const uint4*)g_h1h;   // node row = 8 x uint4
    float acc[8];
#pragma unroll
    for (int j = 0; j < 8; j++) acc[j] = 0.f;
    for (int k = 0; k < deg; k++) {
        int s = __ldg(&g_adj[start + k]);
        uint4 v = h[s * 8 + sl];
        float2 f;
        f = __half22float2(*(__half2*)&v.x); acc[0] += f.x; acc[1] += f.y;
        f = __half22float2(*(((__half2*)&v.x) + 1)); acc[2] += f.x; acc[3] += f.y;
        f = __half22float2(*(__half2*)&v.z); acc[4] += f.x; acc[5] += f.y;
        f = __half22float2(*(((__half2*)&v.z) + 1)); acc[6] += f.x; acc[7] += f.y;
    }
    float inv = deg > 0 ? 1.f / (float)deg : 0.f;
    float4* out = (float4*)&g_agg64[n * 64 + sl * 8];
    out[0] = make_float4(acc[0] * inv, acc[1] * inv, acc[2] * inv, acc[3] * inv);
    out[1] = make_float4(acc[4] * inv, acc[5] * inv, acc[6] * inv, acc[7] * inv);
}

// ---------------------------------------------------------------------------
// conv1 combine: h1 = relu(l2norm(agg32 @ Wl + bl + h0 @ Wr)); emit fp16 copy
__global__ __launch_bounds__(512, 2)
void combine1(const float* __restrict__ wl, const float* __restrict__ bl,
              const float* __restrict__ wr, int N) {
    extern __shared__ char dyn[];
    float2* swl = (float2*)dyn;
    float2* swr = swl + 1024;
    float2* sbias = swr + 1024;
    float* sIn = (float*)(sbias + 32);

    int tid = threadIdx.x;
    for (int i = tid; i < 1024; i += 512) {
        int l = i >> 5, j = i & 31;
        swl[i] = make_float2(wl[l * 64 + j], wl[l * 64 + j + 32]);
        swr[i] = make_float2(wr[l * 64 + j], wr[l * 64 + j + 32]);
    }
    if (tid < 32) sbias[tid] = make_float2(bl[tid], bl[tid + 32]);
    __syncthreads();

    int warp = tid >> 5;
    int lane = tid & 31;
    int n0 = (blockIdx.x * 16 + warp) * 8;
    float* sA = sIn + warp * 512;
    float* sH = sA + 256;

#pragma unroll
    for (int i = 0; i < 8; i++) {
        int n = n0 + i;
        float a = 0.f, h = 0.f;
        if (n < N) {
            a = g_agg32[n * 32 + lane];
            h = g_h0[n * 32 + lane];
        }
        sA[i * 32 + lane] = a;
        sH[i * 32 + lane] = h;
    }
    __syncwarp();

    ull bias_p = ((const ull*)sbias)[lane];
    ull acc[8];
#pragma unroll
    for (int i = 0; i < 8; i++) acc[i] = bias_p;

    const ull* wlp = (const ull*)swl;
    const ull* wrp = (const ull*)swr;
#pragma unroll
    for (int lb = 0; lb < 8; lb++) {
        ull wl0 = wlp[(lb * 4 + 0) * 32 + lane];
        ull wl1 = wlp[(lb * 4 + 1) * 32 + lane];
        ull wl2 = wlp[(lb * 4 + 2) * 32 + lane];
        ull wl3 = wlp[(lb * 4 + 3) * 32 + lane];
        ull wr0 = wrp[(lb * 4 + 0) * 32 + lane];
        ull wr1 = wrp[(lb * 4 + 1) * 32 + lane];
        ull wr2 = wrp[(lb * 4 + 2) * 32 + lane];
        ull wr3 = wrp[(lb * 4 + 3) * 32 + lane];
#pragma unroll
        for (int i = 0; i < 8; i++) {
            float4 a4 = *(const float4*)&sA[i * 32 + lb * 4];
            float4 h4 = *(const float4*)&sH[i * 32 + lb * 4];
            acc[i] = ffma2(dup2(a4.x), wl0, acc[i]);
            acc[i] = ffma2(dup2(h4.x), wr0, acc[i]);
            acc[i] = ffma2(dup2(a4.y), wl1, acc[i]);
            acc[i] = ffma2(dup2(h4.y), wr1, acc[i]);
            acc[i] = ffma2(dup2(a4.z), wl2, acc[i]);
            acc[i] = ffma2(dup2(h4.z), wr2, acc[i]);
            acc[i] = ffma2(dup2(a4.w), wl3, acc[i]);
            acc[i] = ffma2(dup2(h4.w), wr3, acc[i]);
        }
    }

#pragma unroll
    for (int i = 0; i < 8; i++) {
        int n = n0 + i;
        if (n >= N) break;
        float2 o = unpack2(acc[i]);
        float ss = o.x * o.x + o.y * o.y;
#pragma unroll
        for (int off = 16; off > 0; off >>= 1) ss += __shfl_xor_sync(0xffffffffu, ss, off);
        float inv = 1.f / fmaxf(sqrtf(ss), 1e-12f);
        float v0 = fmaxf(o.x * inv, 0.f);
        float v1 = fmaxf(o.y * inv, 0.f);
        g_h1[n * 64 + lane] = v0;
        g_h1[n * 64 + lane + 32] = v1;
        // fp16 copy in plain element order: hh[j] = feature j
        __half* hh = (__half*)&g_h1h[n * 32];
        hh[lane] = __float2half_rn(v0);
        hh[lane + 32] = __float2half_rn(v1);
    }
}

// ---------------------------------------------------------------------------
// conv2 combine + pooling
__global__ __launch_bounds__(512, 2)
void combine2_pool(const int* __restrict__ batch,
                   const float* __restrict__ wl, const float* __restrict__ bl,
                   const float* __restrict__ wr, int N) {
    extern __shared__ char dyn[];
    float2* swl = (float2*)dyn;
    float2* swr = swl + 2048;
    float2* sbias = swr + 2048;
    float* sIn = (float*)(sbias + 32);

    int tid = threadIdx.x;
    for (int i = tid; i < 2048; i += 512) {
        int l = i >> 5, j = i & 31;
        swl[i] = make_float2(wl[l * 64 + j], wl[l * 64 + j + 32]);
        swr[i] = make_float2(wr[l * 64 + j], wr[l * 64 + j + 32]);
    }
    if (tid < 32) sbias[tid] = make_float2(bl[tid], bl[tid + 32]);
    __syncthreads();

    int warp = tid >> 5;
    int lane = tid & 31;
    int n0 = (blockIdx.x * 16 + warp) * 8;
    float* sA = sIn + warp * 1024;
    float* sH = sA + 512;

#pragma unroll
    for (int i = 0; i < 8; i++) {
        int n = n0 + i;
        float a0 = 0.f, a1 = 0.f, h0 = 0.f, h1 = 0.f;
        if (n < N) {
            a0 = g_agg64[n * 64 + lane];
            a1 = g_agg64[n * 64 + 32 + lane];
            h0 = g_h1[n * 64 + lane];
            h1 = g_h1[n * 64 + 32 + lane];
        }
        sA[i * 64 + lane] = a0;
        sA[i * 64 + 32 + lane] = a1;
        sH[i * 64 + lane] = h0;
        sH[i * 64 + 32 + lane] = h1;
    }
    __syncwarp();

    ull bias_p = ((const ull*)sbias)[lane];
    ull acc[8];
#pragma unroll
    for (int i = 0; i < 8; i++) acc[i] = bias_p;

    const ull* wlp = (const ull*)swl;
    const ull* wrp = (const ull*)swr;
#pragma unroll
    for (int lb = 0; lb < 16; lb++) {
        ull wl0 = wlp[(lb * 4 + 0) * 32 + lane];
        ull wl1 = wlp[(lb * 4 + 1) * 32 + lane];
        ull wl2 = wlp[(lb * 4 + 2) * 32 + lane];
        ull wl3 = wlp[(lb * 4 + 3) * 32 + lane];
        ull wr0 = wrp[(lb * 4 + 0) * 32 + lane];
        ull wr1 = wrp[(lb * 4 + 1) * 32 + lane];
        ull wr2 = wrp[(lb * 4 + 2) * 32 + lane];
        ull wr3 = wrp[(lb * 4 + 3) * 32 + lane];
#pragma unroll
        for (int i = 0; i < 8; i++) {
            float4 a4 = *(const float4*)&sA[i * 64 + lb * 4];
            float4 h4 = *(const float4*)&sH[i * 64 + lb * 4];
            acc[i] = ffma2(dup2(a4.x), wl0, acc[i]);
            acc[i] = ffma2(dup2(h4.x), wr0, acc[i]);
            acc[i] = ffma2(dup2(a4.y), wl1, acc[i]);
            acc[i] = ffma2(dup2(h4.y), wr1, acc[i]);
            acc[i] = ffma2(dup2(a4.z), wl2, acc[i]);
            acc[i] = ffma2(dup2(h4.z), wr2, acc[i]);
            acc[i] = ffma2(dup2(a4.w), wl3, acc[i]);
            acc[i] = ffma2(dup2(h4.w), wr3, acc[i]);
        }
    }

#pragma unroll
    for (int i = 0; i < 8; i++) {
        int n = n0 + i;
        if (n >= N) break;
        float2 o = unpack2(acc[i]);
        float ss = o.x * o.x + o.y * o.y;
#pragma unroll
        for (int off = 16; off > 0; off >>= 1) ss += __shfl_xor_sync(0xffffffffu, ss, off);
        float inv = 1.f / fmaxf(sqrtf(ss), 1e-12f);
        float v0 = fmaxf(o.x * inv, 0.f);
        float v1 = fmaxf(o.y * inv, 0.f);
        int b = batch[n];
        red_add_f32(&g_gsum[b * 64 + lane], v0);
        red_add_f32(&g_gsum[b * 64 + 32 + lane], v1);
        if (lane == 0) red_add_f32(&g_gcnt[b], 1.f);
    }
}

// head MLP
__global__ void head_kernel(const float* __restrict__ p1w, const float* __restrict__ p1b,
                            const float* __restrict__ p2w, const float* __restrict__ p2b,
                            const float* __restrict__ ow, const float* __restrict__ ob,
                            float* __restrict__ out) {
    int g = blockIdx.x;
    int t = threadIdx.x;
    __shared__ float sg[64];
    __shared__ float sh[64];
    __shared__ float s2[16];

    float c = g_gcnt[g];
    float invc = 1.f / fmaxf(c, 1.f);
    sg[t] = g_gsum[g * 64 + t] * invc;
    __syncthreads();

    float acc = p1b[t];
#pragma unroll 8
    for (int k = 0; k < 64; k++) acc = fmaf(sg[k], p1w[k * 64 + t], acc);
    sh[t] = fmaxf(acc, 0.f);
    __syncthreads();

    if (t < 16) {
        float a = p2b[t];
#pragma unroll 8
        for (int k = 0; k < 64; k++) a = fmaf(sh[k], p2w[k * 16 + t], a);
        s2[t] = fmaxf(a, 0.f);
    }
    __syncthreads();

    if (t == 0) {
        float a = ob[0];
#pragma unroll
        for (int k = 0; k < 16; k++) a = fmaf(s2[k], ow[k], a);
        out[g] = a;
    }
}

// ---------------------------------------------------------------------------
extern "C" void kernel_launch(void* const* d_in, const int* in_sizes, int n_in,
                              void* d_out, int out_size) {
    const float* x = (const float*)d_in[0];
    const int* ei = (const int*)d_in[1];
    const int* batch = (const int*)d_in[2];

    int base = n_in - 14;
    const float* pre_w = (const float*)d_in[base + 0];
    const float* pre_b = (const float*)d_in[base + 1];
    const float* c1_wl = (const float*)d_in[base + 2];
    const float* c1_bl = (const float*)d_in[base + 3];
    const float* c1_wr = (const float*)d_in[base + 4];
    const float* c2_wl = (const float*)d_in[base + 5];
    const float* c2_bl = (const float*)d_in[base + 6];
    const float* c2_wr = (const float*)d_in[base + 7];
    const float* p1_w = (const float*)d_in[base + 8];
    const float* p1_b = (const float*)d_in[base + 9];
    const float* p2_w = (const float*)d_in[base + 10];
    const float* p2_b = (const float*)d_in[base + 11];
    const float* o_w = (const float*)d_in[base + 12];
    const float* o_b = (const float*)d_in[base + 13];

    int N = in_sizes[0] / 5;
    int E = in_sizes[1] / 2;
    const int* src = ei;
    const int* dst = ei + E;
    float* out = (float*)d_out;

    const int smem1 = 8192 + 8192 + 256 + 16 * 2048;
    const int smem2 = 16384 + 16384 + 256 + 16 * 4096;
    cudaFuncSetAttribute(combine1, cudaFuncAttributeMaxDynamicSharedMemorySize, smem1);
    cudaFuncSetAttribute(combine2_pool, cudaFuncAttributeMaxDynamicSharedMemorySize, smem2);

    int nb = (N + SCAN_B - 1) / SCAN_B;

    zero_small<<<256, 256>>>(N);
    pre_kernel<<<(N + 255) / 256, 256>>>(x, pre_w, pre_b, N);

    hist_kernel<<<(E + 255) / 256, 256>>>(dst, E);
    scan_s1<<<nb, SCAN_B>>>(N);
    scan_s2<<<1, 128>>>(nb);
    scan_s3<<<nb, SCAN_B>>>(N);
    place_kernel<<<(E + 255) / 256, 256>>>(src, dst, E);

    agg1<<<(N + 63) / 64, 256>>>(N);            // 8 nodes/warp, 8 warps/block
    combine1<<<(N + 127) / 128, 512, smem1>>>(c1_wl, c1_bl, c1_wr, N);

    agg2<<<(N + 31) / 32, 256>>>(N);            // 4 nodes/warp, 8 warps/block
    combine2_pool<<<(N + 127) / 128, 512, smem2>>>(batch, c2_wl, c2_bl, c2_wr, N);

    head_kernel<<<out_size, 64>>>(p1_w, p1_b, p2_w, p2_b, o_w, o_b, out);
}

// round 9
// speedup vs baseline: 1.0306x; 1.0306x over previous
#include <cuda_runtime.h>
#include <cuda_fp16.h>
#include <math.h>

// ---------------------------------------------------------------------------
// GNN_11957188952096: pre-linear -> SAGE(32->64) -> SAGE(64->64) -> pool -> MLP
// N=100000 nodes, E=1600000 edges, G=512 graphs
// CSR-by-dst gather aggregation; fp16 neighbor gather (MLP-unrolled), fp32 acc
// ---------------------------------------------------------------------------

#define MAXN 100000
#define MAXE 1600000
#define MAXG 512
#define SCAN_B 1024

__device__ float g_h0[MAXN * 32];      // pre-linear output (fp32, root path)
__device__ __half2 g_h0h[MAXN * 16];   // fp16 copy for gather
__device__ float g_h1[MAXN * 64];      // conv1 output (fp32, root path)
__device__ __half2 g_h1h[MAXN * 32];   // fp16 copy for gather
__device__ float g_agg32[MAXN * 32];   // conv1 neighbor means
__device__ float g_agg64[MAXN * 64];   // conv2 neighbor means
__device__ float g_gsum[MAXG * 64];    // pooled sums
__device__ float g_gcnt[MAXG];         // nodes per graph

__device__ int g_deg[MAXN];
__device__ int g_scan[MAXN];
__device__ int g_rowptr[MAXN];
__device__ int g_fill[MAXN];
__device__ int g_adj[MAXE];
__device__ int g_bsum[256];
__device__ int g_boff[256];

typedef unsigned long long ull;

__device__ __forceinline__ void red_add_f32(float* addr, float v) {
    asm volatile("red.global.add.f32 [%0], %1;"
                 :: "l"(addr), "f"(v) : "memory");
}
__device__ __forceinline__ ull ffma2(ull a, ull b, ull c) {
    ull d;
    asm("fma.rn.f32x2 %0, %1, %2, %3;" : "=l"(d) : "l"(a), "l"(b), "l"(c));
    return d;
}
__device__ __forceinline__ ull dup2(float x) {
    ull d;
    asm("mov.b64 %0, {%1, %1};" : "=l"(d) : "r"(__float_as_uint(x)));
    return d;
}
__device__ __forceinline__ float2 unpack2(ull v) {
    float2 r;
    asm("mov.b64 {%0, %1}, %2;" : "=f"(r.x), "=f"(r.y) : "l"(v));
    return r;
}
__device__ __forceinline__ void acc_u4(float* acc, uint4 v) {
    float2 f;
    f = __half22float2(*(__half2*)&v.x);            acc[0] += f.x; acc[1] += f.y;
    f = __half22float2(*(((__half2*)&v.x) + 1));    acc[2] += f.x; acc[3] += f.y;
    f = __half22float2(*(__half2*)&v.z);            acc[4] += f.x; acc[5] += f.y;
    f = __half22float2(*(((__half2*)&v.z) + 1));    acc[6] += f.x; acc[7] += f.y;
}

// ---------------------------------------------------------------------------
__global__ void zero_small(int N) {
    int i = blockIdx.x * blockDim.x + threadIdx.x;
    int stride = gridDim.x * blockDim.x;
    for (int k = i; k < N; k += stride) g_deg[k] = 0;
    for (int k = i; k < MAXG * 64; k += stride) g_gsum[k] = 0.f;
    for (int k = i; k < MAXG; k += stride) g_gcnt[k] = 0.f;
}

// h0 = relu(x @ pre_w + pre_b); also emit fp16 copy
__global__ void pre_kernel(const float* __restrict__ x,
                           const float* __restrict__ w,
                           const float* __restrict__ b, int N) {
    __shared__ float sw[5 * 32];
    __shared__ float sb[32];
    for (int i = threadIdx.x; i < 160; i += blockDim.x) sw[i] = w[i];
    if (threadIdx.x < 32) sb[threadIdx.x] = b[threadIdx.x];
    __syncthreads();
    int n = blockIdx.x * blockDim.x + threadIdx.x;
    if (n >= N) return;
    float xv[5];
#pragma unroll
    for (int k = 0; k < 5; k++) xv[k] = x[n * 5 + k];
    float o[32];
#pragma unroll
    for (int j = 0; j < 32; j++) {
        float acc = sb[j];
#pragma unroll
        for (int k = 0; k < 5; k++) acc = fmaf(xv[k], sw[k * 32 + j], acc);
        o[j] = fmaxf(acc, 0.f);
        g_h0[n * 32 + j] = o[j];
    }
#pragma unroll
    for (int j = 0; j < 16; j++)
        g_h0h[n * 16 + j] = __floats2half2_rn(o[2 * j], o[2 * j + 1]);
}

// ---------------------------------------------------------------------------
// CSR construction
__global__ void hist_kernel(const int* __restrict__ dst, int E) {
    int e = blockIdx.x * blockDim.x + threadIdx.x;
    if (e < E) atomicAdd(&g_deg[dst[e]], 1);
}

__global__ void scan_s1(int N) {
    __shared__ int buf0[SCAN_B], buf1[SCAN_B];
    int t = threadIdx.x;
    int g = blockIdx.x * SCAN_B + t;
    buf0[t] = (g < N) ? g_deg[g] : 0;
    int* a = buf0; int* b = buf1;
#pragma unroll
    for (int off = 1; off < SCAN_B; off <<= 1) {
        __syncthreads();
        b[t] = (t >= off) ? a[t] + a[t - off] : a[t];
        int* tmp = a; a = b; b = tmp;
    }
    __syncthreads();
    if (g < N) g_scan[g] = a[t];
    if (t == SCAN_B - 1) g_bsum[blockIdx.x] = a[t];
}

// exclusive scan over <=128 block sums
__global__ void scan_s2(int nb) {
    __shared__ int s0[128], s1[128];
    int t = threadIdx.x;
    int v = (t < nb) ? g_bsum[t] : 0;
    s0[t] = v;
    int* a = s0; int* b = s1;
#pragma unroll
    for (int off = 1; off < 128; off <<= 1) {
        __syncthreads();
        b[t] = (t >= off) ? a[t] + a[t - off] : a[t];
        int* tmp = a; a = b; b = tmp;
    }
    __syncthreads();
    if (t < nb) g_boff[t] = a[t] - v;
}

__global__ void scan_s3(int N) {
    int g = blockIdx.x * SCAN_B + threadIdx.x;
    if (g < N) {
        g_rowptr[g] = g_scan[g] - g_deg[g] + g_boff[blockIdx.x];
        g_fill[g] = 0;
    }
}

__global__ void place_kernel(const int* __restrict__ src, const int* __restrict__ dst,
                             int E) {
    int e = blockIdx.x * blockDim.x + threadIdx.x;
    if (e >= E) return;
    int d = dst[e];
    int pos = g_rowptr[d] + atomicAdd(&g_fill[d], 1);
    g_adj[pos] = src[e];
}

// ---------------------------------------------------------------------------
// gather agg conv1 (fp16): 4 lanes x uint4 per node, 8 nodes/warp, MLP=4 unroll
__global__ void agg1(int N) {
    int gw = (blockIdx.x * blockDim.x + threadIdx.x) >> 5;
    int lane = threadIdx.x & 31;
    int sub = lane >> 2, sl = lane & 3;
    int n = gw * 8 + sub;
    if (n >= N) return;
    int start = g_rowptr[n];
    int deg = g_deg[n];
    const uint4* h = (const uint4*)g_h0h;   // node row = 4 x uint4
    float acc[8];
#pragma unroll
    for (int j = 0; j < 8; j++) acc[j] = 0.f;
    const int* adj = &g_adj[start];
    int k = 0;
    for (; k + 4 <= deg; k += 4) {
        int s0 = __ldg(&adj[k + 0]);
        int s1 = __ldg(&adj[k + 1]);
        int s2 = __ldg(&adj[k + 2]);
        int s3 = __ldg(&adj[k + 3]);
        uint4 v0 = h[s0 * 4 + sl];
        uint4 v1 = h[s1 * 4 + sl];
        uint4 v2 = h[s2 * 4 + sl];
        uint4 v3 = h[s3 * 4 + sl];
        acc_u4(acc, v0); acc_u4(acc, v1); acc_u4(acc, v2); acc_u4(acc, v3);
    }
    if (k + 2 <= deg) {
        int s0 = __ldg(&adj[k + 0]);
        int s1 = __ldg(&adj[k + 1]);
        uint4 v0 = h[s0 * 4 + sl];
        uint4 v1 = h[s1 * 4 + sl];
        acc_u4(acc, v0); acc_u4(acc, v1);
        k += 2;
    }
    if (k < deg) {
        int s0 = __ldg(&adj[k]);
        uint4 v0 = h[s0 * 4 + sl];
        acc_u4(acc, v0);
    }
    float inv = deg > 0 ? 1.f / (float)deg : 0.f;
    float4* out = (float4*)&g_agg32[n * 32 + sl * 8];
    out[0] = make_float4(acc[0] * inv, acc[1] * inv, acc[2] * inv, acc[3] * inv);
    out[1] = make_float4(acc[4] * inv, acc[5] * inv, acc[6] * inv, acc[7] * inv);
}

// gather agg conv2 (fp16): 8 lanes x uint4 per node, 4 nodes/warp, MLP=4 unroll
__global__ void agg2(int N) {
    int gw = (blockIdx.x * blockDim.x + threadIdx.x) >> 5;
    int lane = threadIdx.x & 31;
    int sub = lane >> 3, sl = lane & 7;
    int n = gw * 4 + sub;
    if (n >= N) return;
    int start = g_rowptr[n];
    int deg = g_deg[n];
    const uint4* h = (const uint4*)g_h1h;   // node row = 8 x uint4
    float acc[8];
#pragma unroll
    for (int j = 0; j < 8; j++) acc[j] = 0.f;
    const int* adj = &g_adj[start];
    int k = 0;
    for (; k + 4 <= deg; k += 4) {
        int s0 = __ldg(&adj[k + 0]);
        int s1 = __ldg(&adj[k + 1]);
        int s2 = __ldg(&adj[k + 2]);
        int s3 = __ldg(&adj[k + 3]);
        uint4 v0 = h[s0 * 8 + sl];
        uint4 v1 = h[s1 * 8 + sl];
        uint4 v2 = h[s2 * 8 + sl];
        uint4 v3 = h[s3 * 8 + sl];
        acc_u4(acc, v0); acc_u4(acc, v1); acc_u4(acc, v2); acc_u4(acc, v3);
    }
    if (k + 2 <= deg) {
        int s0 = __ldg(&adj[k + 0]);
        int s1 = __ldg(&adj[k + 1]);
        uint4 v0 = h[s0 * 8 + sl];
        uint4 v1 = h[s1 * 8 + sl];
        acc_u4(acc, v0); acc_u4(acc, v1);
        k += 2;
    }
    if (k < deg) {
        int s0 = __ldg(&adj[k]);
        uint4 v0 = h[s0 * 8 + sl];
        acc_u4(acc, v0);
    }
    float inv = deg > 0 ? 1.f / (float)deg : 0.f;
    float4* out = (float4*)&g_agg64[n * 64 + sl * 8];
    out[0] = make_float4(acc[0] * inv, acc[1] * inv, acc[2] * inv, acc[3] * inv);
    out[1] = make_float4(acc[4] * inv, acc[5] * inv, acc[6] * inv, acc[7] * inv);
}

// ---------------------------------------------------------------------------
// conv1 combine: h1 = relu(l2norm(agg32 @ Wl + bl + h0 @ Wr)); emit fp16 copy
__global__ __launch_bounds__(512, 2)
void combine1(const float* __restrict__ wl, const float* __restrict__ bl,
              const float* __restrict__ wr, int N) {
    extern __shared__ char dyn[];
    float2* swl = (float2*)dyn;
    float2* swr = swl + 1024;
    float2* sbias = swr + 1024;
    float* sIn = (float*)(sbias + 32);

    int tid = threadIdx.x;
    for (int i = tid; i < 1024; i += 512) {
        int l = i >> 5, j = i & 31;
        swl[i] = make_float2(wl[l * 64 + j], wl[l * 64 + j + 32]);
        swr[i] = make_float2(wr[l * 64 + j], wr[l * 64 + j + 32]);
    }
    if (tid < 32) sbias[tid] = make_float2(bl[tid], bl[tid + 32]);
    __syncthreads();

    int warp = tid >> 5;
    int lane = tid & 31;
    int n0 = (blockIdx.x * 16 + warp) * 8;
    float* sA = sIn + warp * 512;
    float* sH = sA + 256;

#pragma unroll
    for (int i = 0; i < 8; i++) {
        int n = n0 + i;
        float a = 0.f, h = 0.f;
        if (n < N) {
            a = g_agg32[n * 32 + lane];
            h = g_h0[n * 32 + lane];
        }
        sA[i * 32 + lane] = a;
        sH[i * 32 + lane] = h;
    }
    __syncwarp();

    ull bias_p = ((const ull*)sbias)[lane];
    ull acc[8];
#pragma unroll
    for (int i = 0; i < 8; i++) acc[i] = bias_p;

    const ull* wlp = (const ull*)swl;
    const ull* wrp = (const ull*)swr;
#pragma unroll
    for (int lb = 0; lb < 8; lb++) {
        ull wl0 = wlp[(lb * 4 + 0) * 32 + lane];
        ull wl1 = wlp[(lb * 4 + 1) * 32 + lane];
        ull wl2 = wlp[(lb * 4 + 2) * 32 + lane];
        ull wl3 = wlp[(lb * 4 + 3) * 32 + lane];
        ull wr0 = wrp[(lb * 4 + 0) * 32 + lane];
        ull wr1 = wrp[(lb * 4 + 1) * 32 + lane];
        ull wr2 = wrp[(lb * 4 + 2) * 32 + lane];
        ull wr3 = wrp[(lb * 4 + 3) * 32 + lane];
#pragma unroll
        for (int i = 0; i < 8; i++) {
            float4 a4 = *(const float4*)&sA[i * 32 + lb * 4];
            float4 h4 = *(const float4*)&sH[i * 32 + lb * 4];
            acc[i] = ffma2(dup2(a4.x), wl0, acc[i]);
            acc[i] = ffma2(dup2(h4.x), wr0, acc[i]);
            acc[i] = ffma2(dup2(a4.y), wl1, acc[i]);
            acc[i] = ffma2(dup2(h4.y), wr1, acc[i]);
            acc[i] = ffma2(dup2(a4.z), wl2, acc[i]);
            acc[i] = ffma2(dup2(h4.z), wr2, acc[i]);
            acc[i] = ffma2(dup2(a4.w), wl3, acc[i]);
            acc[i] = ffma2(dup2(h4.w), wr3, acc[i]);
        }
    }

#pragma unroll
    for (int i = 0; i < 8; i++) {
        int n = n0 + i;
        if (n >= N) break;
        float2 o = unpack2(acc[i]);
        float ss = o.x * o.x + o.y * o.y;
#pragma unroll
        for (int off = 16; off > 0; off >>= 1) ss += __shfl_xor_sync(0xffffffffu, ss, off);
        float inv = 1.f / fmaxf(sqrtf(ss), 1e-12f);
        float v0 = fmaxf(o.x * inv, 0.f);
        float v1 = fmaxf(o.y * inv, 0.f);
        g_h1[n * 64 + lane] = v0;
        g_h1[n * 64 + lane + 32] = v1;
        __half* hh = (__half*)&g_h1h[n * 32];
        hh[lane] = __float2half_rn(v0);
        hh[lane + 32] = __float2half_rn(v1);
    }
}

// ---------------------------------------------------------------------------
// conv2 combine + pooling
__global__ __launch_bounds__(512, 2)
void combine2_pool(const int* __restrict__ batch,
                   const float* __restrict__ wl, const float* __restrict__ bl,
                   const float* __restrict__ wr, int N) {
    extern __shared__ char dyn[];
    float2* swl = (float2*)dyn;
    float2* swr = swl + 2048;
    float2* sbias = swr + 2048;
    float* sIn = (float*)(sbias + 32);

    int tid = threadIdx.x;
    for (int i = tid; i < 2048; i += 512) {
        int l = i >> 5, j = i & 31;
        swl[i] = make_float2(wl[l * 64 + j], wl[l * 64 + j + 32]);
        swr[i] = make_float2(wr[l * 64 + j], wr[l * 64 + j + 32]);
    }
    if (tid < 32) sbias[tid] = make_float2(bl[tid], bl[tid + 32]);
    __syncthreads();

    int warp = tid >> 5;
    int lane = tid & 31;
    int n0 = (blockIdx.x * 16 + warp) * 8;
    float* sA = sIn + warp * 1024;
    float* sH = sA + 512;

#pragma unroll
    for (int i = 0; i < 8; i++) {
        int n = n0 + i;
        float a0 = 0.f, a1 = 0.f, h0 = 0.f, h1 = 0.f;
        if (n < N) {
            a0 = g_agg64[n * 64 + lane];
            a1 = g_agg64[n * 64 + 32 + lane];
            h0 = g_h1[n * 64 + lane];
            h1 = g_h1[n * 64 + 32 + lane];
        }
        sA[i * 64 + lane] = a0;
        sA[i * 64 + 32 + lane] = a1;
        sH[i * 64 + lane] = h0;
        sH[i * 64 + 32 + lane] = h1;
    }
    __syncwarp();

    ull bias_p = ((const ull*)sbias)[lane];
    ull acc[8];
#pragma unroll
    for (int i = 0; i < 8; i++) acc[i] = bias_p;

    const ull* wlp = (const ull*)swl;
    const ull* wrp = (const ull*)swr;
#pragma unroll
    for (int lb = 0; lb < 16; lb++) {
        ull wl0 = wlp[(lb * 4 + 0) * 32 + lane];
        ull wl1 = wlp[(lb * 4 + 1) * 32 + lane];
        ull wl2 = wlp[(lb * 4 + 2) * 32 + lane];
        ull wl3 = wlp[(lb * 4 + 3) * 32 + lane];
        ull wr0 = wrp[(lb * 4 + 0) * 32 + lane];
        ull wr1 = wrp[(lb * 4 + 1) * 32 + lane];
        ull wr2 = wrp[(lb * 4 + 2) * 32 + lane];
        ull wr3 = wrp[(lb * 4 + 3) * 32 + lane];
#pragma unroll
        for (int i = 0; i < 8; i++) {
            float4 a4 = *(const float4*)&sA[i * 64 + lb * 4];
            float4 h4 = *(const float4*)&sH[i * 64 + lb * 4];
            acc[i] = ffma2(dup2(a4.x), wl0, acc[i]);
            acc[i] = ffma2(dup2(h4.x), wr0, acc[i]);
            acc[i] = ffma2(dup2(a4.y), wl1, acc[i]);
            acc[i] = ffma2(dup2(h4.y), wr1, acc[i]);
            acc[i] = ffma2(dup2(a4.z), wl2, acc[i]);
            acc[i] = ffma2(dup2(h4.z), wr2, acc[i]);
            acc[i] = ffma2(dup2(a4.w), wl3, acc[i]);
            acc[i] = ffma2(dup2(h4.w), wr3, acc[i]);
        }
    }

#pragma unroll
    for (int i = 0; i < 8; i++) {
        int n = n0 + i;
        if (n >= N) break;
        float2 o = unpack2(acc[i]);
        float ss = o.x * o.x + o.y * o.y;
#pragma unroll
        for (int off = 16; off > 0; off >>= 1) ss += __shfl_xor_sync(0xffffffffu, ss, off);
        float inv = 1.f / fmaxf(sqrtf(ss), 1e-12f);
        float v0 = fmaxf(o.x * inv, 0.f);
        float v1 = fmaxf(o.y * inv, 0.f);
        int b = batch[n];
        red_add_f32(&g_gsum[b * 64 + lane], v0);
        red_add_f32(&g_gsum[b * 64 + 32 + lane], v1);
        if (lane == 0) red_add_f32(&g_gcnt[b], 1.f);
    }
}

// head MLP
__global__ void head_kernel(const float* __restrict__ p1w, const float* __restrict__ p1b,
                            const float* __restrict__ p2w, const float* __restrict__ p2b,
                            const float* __restrict__ ow, const float* __restrict__ ob,
                            float* __restrict__ out) {
    int g = blockIdx.x;
    int t = threadIdx.x;
    __shared__ float sg[64];
    __shared__ float sh[64];
    __shared__ float s2[16];

    float c = g_gcnt[g];
    float invc = 1.f / fmaxf(c, 1.f);
    sg[t] = g_gsum[g * 64 + t] * invc;
    __syncthreads();

    float acc = p1b[t];
#pragma unroll 8
    for (int k = 0; k < 64; k++) acc = fmaf(sg[k], p1w[k * 64 + t], acc);
    sh[t] = fmaxf(acc, 0.f);
    __syncthreads();

    if (t < 16) {
        float a = p2b[t];
#pragma unroll 8
        for (int k = 0; k < 64; k++) a = fmaf(sh[k], p2w[k * 16 + t], a);
        s2[t] = fmaxf(a, 0.f);
    }
    __syncthreads();

    if (t == 0) {
        float a = ob[0];
#pragma unroll
        for (int k = 0; k < 16; k++) a = fmaf(s2[k], ow[k], a);
        out[g] = a;
    }
}

// ---------------------------------------------------------------------------
extern "C" void kernel_launch(void* const* d_in, const int* in_sizes, int n_in,
                              void* d_out, int out_size) {
    const float* x = (const float*)d_in[0];
    const int* ei = (const int*)d_in[1];
    const int* batch = (const int*)d_in[2];

    int base = n_in - 14;
    const float* pre_w = (const float*)d_in[base + 0];
    const float* pre_b = (const float*)d_in[base + 1];
    const float* c1_wl = (const float*)d_in[base + 2];
    const float* c1_bl = (const float*)d_in[base + 3];
    const float* c1_wr = (const float*)d_in[base + 4];
    const float* c2_wl = (const float*)d_in[base + 5];
    const float* c2_bl = (const float*)d_in[base + 6];
    const float* c2_wr = (const float*)d_in[base + 7];
    const float* p1_w = (const float*)d_in[base + 8];
    const float* p1_b = (const float*)d_in[base + 9];
    const float* p2_w = (const float*)d_in[base + 10];
    const float* p2_b = (const float*)d_in[base + 11];
    const float* o_w = (const float*)d_in[base + 12];
    const float* o_b = (const float*)d_in[base + 13];

    int N = in_sizes[0] / 5;
    int E = in_sizes[1] / 2;
    const int* src = ei;
    const int* dst = ei + E;
    float* out = (float*)d_out;

    const int smem1 = 8192 + 8192 + 256 + 16 * 2048;
    const int smem2 = 16384 + 16384 + 256 + 16 * 4096;
    cudaFuncSetAttribute(combine1, cudaFuncAttributeMaxDynamicSharedMemorySize, smem1);
    cudaFuncSetAttribute(combine2_pool, cudaFuncAttributeMaxDynamicSharedMemorySize, smem2);

    int nb = (N + SCAN_B - 1) / SCAN_B;

    zero_small<<<256, 256>>>(N);
    pre_kernel<<<(N + 255) / 256, 256>>>(x, pre_w, pre_b, N);

    hist_kernel<<<(E + 255) / 256, 256>>>(dst, E);
    scan_s1<<<nb, SCAN_B>>>(N);
    scan_s2<<<1, 128>>>(nb);
    scan_s3<<<nb, SCAN_B>>>(N);
    place_kernel<<<(E + 255) / 256, 256>>>(src, dst, E);

    agg1<<<(N + 63) / 64, 256>>>(N);            // 8 nodes/warp, 8 warps/block
    combine1<<<(N + 127) / 128, 512, smem1>>>(c1_wl, c1_bl, c1_wr, N);

    agg2<<<(N + 31) / 32, 256>>>(N);            // 4 nodes/warp, 8 warps/block
    combine2_pool<<<(N + 127) / 128, 512, smem2>>>(batch, c2_wl, c2_bl, c2_wr, N);

    head_kernel<<<out_size, 64>>>(p1_w, p1_b, p2_w, p2_b, o_w, o_b, out);
}

// round 10
// speedup vs baseline: 1.0932x; 1.0607x over previous
#include <cuda_runtime.h>
#include <cuda_fp16.h>
#include <math.h>

// ---------------------------------------------------------------------------
// GNN_11957188952096: pre-linear -> SAGE(32->64) -> SAGE(64->64) -> pool -> MLP
// N=100000 nodes, E=1600000 edges, G=512 graphs
// CSR gather fused into combine kernels; single-kernel lookback scan.
// ---------------------------------------------------------------------------

#define MAXN 100000
#define MAXE 1600000
#define MAXG 512
#define SCAN_B 1024
#define AFLAG (1u << 30)
#define PFLAG (2u << 30)

__device__ float g_h0[MAXN * 32];      // pre-linear output (fp32 root path)
__device__ __half2 g_h0h[MAXN * 16];   // fp16 copy for gather
__device__ float g_h1[MAXN * 64];      // conv1 output (fp32 root path)
__device__ __half2 g_h1h[MAXN * 32];   // fp16 copy for gather
__device__ float g_gsum[MAXG * 64];
__device__ float g_gcnt[MAXG];

__device__ int g_deg[MAXN];
__device__ int g_rowptr[MAXN];
__device__ int g_fill[MAXN];
__device__ int g_adj[MAXE];
__device__ unsigned g_state[128];      // lookback scan state

typedef unsigned long long ull;

__device__ __forceinline__ void red_add_f32(float* addr, float v) {
    asm volatile("red.global.add.f32 [%0], %1;"
                 :: "l"(addr), "f"(v) : "memory");
}
__device__ __forceinline__ ull ffma2(ull a, ull b, ull c) {
    ull d;
    asm("fma.rn.f32x2 %0, %1, %2, %3;" : "=l"(d) : "l"(a), "l"(b), "l"(c));
    return d;
}
__device__ __forceinline__ ull dup2(float x) {
    ull d;
    asm("mov.b64 %0, {%1, %1};" : "=l"(d) : "r"(__float_as_uint(x)));
    return d;
}
__device__ __forceinline__ float2 unpack2(ull v) {
    float2 r;
    asm("mov.b64 {%0, %1}, %2;" : "=f"(r.x), "=f"(r.y) : "l"(v));
    return r;
}
__device__ __forceinline__ void acc_u4(float* acc, uint4 v) {
    float2 f;
    f = __half22float2(*(__half2*)&v.x);            acc[0] += f.x; acc[1] += f.y;
    f = __half22float2(*(((__half2*)&v.x) + 1));    acc[2] += f.x; acc[3] += f.y;
    f = __half22float2(*(__half2*)&v.z);            acc[4] += f.x; acc[5] += f.y;
    f = __half22float2(*(((__half2*)&v.z) + 1));    acc[6] += f.x; acc[7] += f.y;
}

// ---------------------------------------------------------------------------
__global__ void zero_small(int N) {
    int i = blockIdx.x * blockDim.x + threadIdx.x;
    int stride = gridDim.x * blockDim.x;
    for (int k = i; k < N; k += stride) g_deg[k] = 0;
    for (int k = i; k < MAXG * 64; k += stride) g_gsum[k] = 0.f;
    for (int k = i; k < MAXG; k += stride) g_gcnt[k] = 0.f;
    if (i < 128) g_state[i] = 0u;
}

// in-degree histogram
__global__ void hist_kernel(const int* __restrict__ dst, int E) {
    int e = blockIdx.x * blockDim.x + threadIdx.x;
    if (e < E) atomicAdd(&g_deg[dst[e]], 1);
}

// single-kernel exclusive scan via decoupled lookback (98 blocks, all resident)
__global__ void scan_kernel(int N) {
    __shared__ int buf0[SCAN_B], buf1[SCAN_B];
    __shared__ int s_run;
    int t = threadIdx.x, bid = blockIdx.x;
    int g = bid * SCAN_B + t;
    int v = (g < N) ? g_deg[g] : 0;
    buf0[t] = v;
    int* a = buf0; int* b = buf1;
#pragma unroll
    for (int off = 1; off < SCAN_B; off <<= 1) {
        __syncthreads();
        b[t] = (t >= off) ? a[t] + a[t - off] : a[t];
        int* tmp = a; a = b; b = tmp;
    }
    __syncthreads();
    int incl = a[t];
    int bsum = a[SCAN_B - 1];
    if (t == 0) {
        if (bid == 0) {
            atomicExch(&g_state[0], PFLAG | (unsigned)bsum);
            s_run = 0;
        } else {
            atomicExch(&g_state[bid], AFLAG | (unsigned)bsum);
            int run = 0;
            for (int j = bid - 1; j >= 0; j--) {
                unsigned s;
                do { s = atomicAdd(&g_state[j], 0u); } while ((s >> 30) == 0);
                run += (int)(s & 0x3FFFFFFFu);
                if (s & PFLAG) break;  // hit a full prefix
            }
            atomicExch(&g_state[bid], PFLAG | (unsigned)(run + bsum));
            s_run = run;
        }
    }
    __syncthreads();
    if (g < N) {
        g_rowptr[g] = incl - v + s_run;   // exclusive prefix
        g_fill[g] = 0;
    }
}

__global__ void place_kernel(const int* __restrict__ src, const int* __restrict__ dst,
                             int E) {
    int e = blockIdx.x * blockDim.x + threadIdx.x;
    if (e >= E) return;
    int d = dst[e];
    int pos = g_rowptr[d] + atomicAdd(&g_fill[d], 1);
    g_adj[pos] = src[e];
}

// h0 = relu(x @ pre_w + pre_b); fp32 + fp16 copies
__global__ void pre_kernel(const float* __restrict__ x,
                           const float* __restrict__ w,
                           const float* __restrict__ b, int N) {
    __shared__ float sw[5 * 32];
    __shared__ float sb[32];
    for (int i = threadIdx.x; i < 160; i += blockDim.x) sw[i] = w[i];
    if (threadIdx.x < 32) sb[threadIdx.x] = b[threadIdx.x];
    __syncthreads();
    int n = blockIdx.x * blockDim.x + threadIdx.x;
    if (n >= N) return;
    float xv[5];
#pragma unroll
    for (int k = 0; k < 5; k++) xv[k] = x[n * 5 + k];
    float o[32];
#pragma unroll
    for (int j = 0; j < 32; j++) {
        float acc = sb[j];
#pragma unroll
        for (int k = 0; k < 5; k++) acc = fmaf(xv[k], sw[k * 32 + j], acc);
        o[j] = fmaxf(acc, 0.f);
        g_h0[n * 32 + j] = o[j];
    }
#pragma unroll
    for (int j = 0; j < 16; j++)
        g_h0h[n * 16 + j] = __floats2half2_rn(o[2 * j], o[2 * j + 1]);
}

// ---------------------------------------------------------------------------
// conv1 fused: gather mean(h0h) into smem, then combine; emits h1 fp32+fp16
__global__ __launch_bounds__(512, 2)
void conv1(const float* __restrict__ wl, const float* __restrict__ bl,
           const float* __restrict__ wr, int N) {
    extern __shared__ char dyn[];
    float2* swl = (float2*)dyn;                 // 8192 B
    float2* swr = swl + 1024;                   // 8192 B
    float2* sbias = swr + 1024;                 // 256 B
    float* sIn = (float*)(sbias + 32);          // 16 * 2048 B

    int tid = threadIdx.x;
    for (int i = tid; i < 1024; i += 512) {
        int l = i >> 5, j = i & 31;
        swl[i] = make_float2(wl[l * 64 + j], wl[l * 64 + j + 32]);
        swr[i] = make_float2(wr[l * 64 + j], wr[l * 64 + j + 32]);
    }
    if (tid < 32) sbias[tid] = make_float2(bl[tid], bl[tid + 32]);
    __syncthreads();

    int warp = tid >> 5;
    int lane = tid & 31;
    int n0 = (blockIdx.x * 16 + warp) * 8;
    float* sA = sIn + warp * 512;
    float* sH = sA + 256;

    // gather phase: 4 lanes per node (8 nodes per warp)
    {
        int sub = lane >> 2, sl = lane & 3;
        int n = n0 + sub;
        float acc[8];
#pragma unroll
        for (int j = 0; j < 8; j++) acc[j] = 0.f;
        int deg = 0;
        if (n < N) {
            int start = g_rowptr[n];
            deg = g_deg[n];
            const uint4* h = (const uint4*)g_h0h;   // row = 4 uint4
            const int* adj = &g_adj[start];
            int k = 0;
            for (; k + 4 <= deg; k += 4) {
                int s0 = __ldg(&adj[k + 0]);
                int s1 = __ldg(&adj[k + 1]);
                int s2 = __ldg(&adj[k + 2]);
                int s3 = __ldg(&adj[k + 3]);
                uint4 v0 = h[s0 * 4 + sl];
                uint4 v1 = h[s1 * 4 + sl];
                uint4 v2 = h[s2 * 4 + sl];
                uint4 v3 = h[s3 * 4 + sl];
                acc_u4(acc, v0); acc_u4(acc, v1); acc_u4(acc, v2); acc_u4(acc, v3);
            }
            if (k + 2 <= deg) {
                int s0 = __ldg(&adj[k + 0]);
                int s1 = __ldg(&adj[k + 1]);
                uint4 v0 = h[s0 * 4 + sl];
                uint4 v1 = h[s1 * 4 + sl];
                acc_u4(acc, v0); acc_u4(acc, v1);
                k += 2;
            }
            if (k < deg) {
                int s0 = __ldg(&adj[k]);
                uint4 v0 = h[s0 * 4 + sl];
                acc_u4(acc, v0);
            }
        }
        float inv = deg > 0 ? 1.f / (float)deg : 0.f;
        float4* o = (float4*)&sA[sub * 32 + sl * 8];
        o[0] = make_float4(acc[0] * inv, acc[1] * inv, acc[2] * inv, acc[3] * inv);
        o[1] = make_float4(acc[4] * inv, acc[5] * inv, acc[6] * inv, acc[7] * inv);
    }

    // root feature staging
#pragma unroll
    for (int i = 0; i < 8; i++) {
        int n = n0 + i;
        sH[i * 32 + lane] = (n < N) ? g_h0[n * 32 + lane] : 0.f;
    }
    __syncwarp();

    // combine phase
    ull bias_p = ((const ull*)sbias)[lane];
    ull acc[8];
#pragma unroll
    for (int i = 0; i < 8; i++) acc[i] = bias_p;

    const ull* wlp = (const ull*)swl;
    const ull* wrp = (const ull*)swr;
#pragma unroll
    for (int lb = 0; lb < 8; lb++) {
        ull wl0 = wlp[(lb * 4 + 0) * 32 + lane];
        ull wl1 = wlp[(lb * 4 + 1) * 32 + lane];
        ull wl2 = wlp[(lb * 4 + 2) * 32 + lane];
        ull wl3 = wlp[(lb * 4 + 3) * 32 + lane];
        ull wr0 = wrp[(lb * 4 + 0) * 32 + lane];
        ull wr1 = wrp[(lb * 4 + 1) * 32 + lane];
        ull wr2 = wrp[(lb * 4 + 2) * 32 + lane];
        ull wr3 = wrp[(lb * 4 + 3) * 32 + lane];
#pragma unroll
        for (int i = 0; i < 8; i++) {
            float4 a4 = *(const float4*)&sA[i * 32 + lb * 4];
            float4 h4 = *(const float4*)&sH[i * 32 + lb * 4];
            acc[i] = ffma2(dup2(a4.x), wl0, acc[i]);
            acc[i] = ffma2(dup2(h4.x), wr0, acc[i]);
            acc[i] = ffma2(dup2(a4.y), wl1, acc[i]);
            acc[i] = ffma2(dup2(h4.y), wr1, acc[i]);
            acc[i] = ffma2(dup2(a4.z), wl2, acc[i]);
            acc[i] = ffma2(dup2(h4.z), wr2, acc[i]);
            acc[i] = ffma2(dup2(a4.w), wl3, acc[i]);
            acc[i] = ffma2(dup2(h4.w), wr3, acc[i]);
        }
    }

#pragma unroll
    for (int i = 0; i < 8; i++) {
        int n = n0 + i;
        if (n >= N) break;
        float2 o = unpack2(acc[i]);
        float ss = o.x * o.x + o.y * o.y;
#pragma unroll
        for (int off = 16; off > 0; off >>= 1) ss += __shfl_xor_sync(0xffffffffu, ss, off);
        float inv = 1.f / fmaxf(sqrtf(ss), 1e-12f);
        float v0 = fmaxf(o.x * inv, 0.f);
        float v1 = fmaxf(o.y * inv, 0.f);
        g_h1[n * 64 + lane] = v0;
        g_h1[n * 64 + lane + 32] = v1;
        __half* hh = (__half*)&g_h1h[n * 32];
        hh[lane] = __float2half_rn(v0);
        hh[lane + 32] = __float2half_rn(v1);
    }
}

// ---------------------------------------------------------------------------
// conv2 fused: gather mean(h1h) into smem (2 passes), combine, pool
__global__ __launch_bounds__(512, 2)
void conv2(const int* __restrict__ batch,
           const float* __restrict__ wl, const float* __restrict__ bl,
           const float* __restrict__ wr, int N) {
    extern __shared__ char dyn[];
    float2* swl = (float2*)dyn;                 // 16384 B
    float2* swr = swl + 2048;                   // 16384 B
    float2* sbias = swr + 2048;                 // 256 B
    float* sIn = (float*)(sbias + 32);          // 16 * 4096 B

    int tid = threadIdx.x;
    for (int i = tid; i < 2048; i += 512) {
        int l = i >> 5, j = i & 31;
        swl[i] = make_float2(wl[l * 64 + j], wl[l * 64 + j + 32]);
        swr[i] = make_float2(wr[l * 64 + j], wr[l * 64 + j + 32]);
    }
    if (tid < 32) sbias[tid] = make_float2(bl[tid], bl[tid + 32]);
    __syncthreads();

    int warp = tid >> 5;
    int lane = tid & 31;
    int n0 = (blockIdx.x * 16 + warp) * 8;
    float* sA = sIn + warp * 1024;
    float* sH = sA + 512;

    // gather phase: 8 lanes per node, 4 nodes per pass, 2 passes
#pragma unroll
    for (int p = 0; p < 2; p++) {
        int sub = lane >> 3, sl = lane & 7;
        int i = p * 4 + sub;
        int n = n0 + i;
        float acc[8];
#pragma unroll
        for (int j = 0; j < 8; j++) acc[j] = 0.f;
        int deg = 0;
        if (n < N) {
            int start = g_rowptr[n];
            deg = g_deg[n];
            const uint4* h = (const uint4*)g_h1h;   // row = 8 uint4
            const int* adj = &g_adj[start];
            int k = 0;
            for (; k + 4 <= deg; k += 4) {
                int s0 = __ldg(&adj[k + 0]);
                int s1 = __ldg(&adj[k + 1]);
                int s2 = __ldg(&adj[k + 2]);
                int s3 = __ldg(&adj[k + 3]);
                uint4 v0 = h[s0 * 8 + sl];
                uint4 v1 = h[s1 * 8 + sl];
                uint4 v2 = h[s2 * 8 + sl];
                uint4 v3 = h[s3 * 8 + sl];
                acc_u4(acc, v0); acc_u4(acc, v1); acc_u4(acc, v2); acc_u4(acc, v3);
            }
            if (k + 2 <= deg) {
                int s0 = __ldg(&adj[k + 0]);
                int s1 = __ldg(&adj[k + 1]);
                uint4 v0 = h[s0 * 8 + sl];
                uint4 v1 = h[s1 * 8 + sl];
                acc_u4(acc, v0); acc_u4(acc, v1);
                k += 2;
            }
            if (k < deg) {
                int s0 = __ldg(&adj[k]);
                uint4 v0 = h[s0 * 8 + sl];
                acc_u4(acc, v0);
            }
        }
        float inv = deg > 0 ? 1.f / (float)deg : 0.f;
        float4* o = (float4*)&sA[i * 64 + sl * 8];
        o[0] = make_float4(acc[0] * inv, acc[1] * inv, acc[2] * inv, acc[3] * inv);
        o[1] = make_float4(acc[4] * inv, acc[5] * inv, acc[6] * inv, acc[7] * inv);
    }

    // root feature staging
#pragma unroll
    for (int i = 0; i < 8; i++) {
        int n = n0 + i;
        float h0 = 0.f, h1 = 0.f;
        if (n < N) {
            h0 = g_h1[n * 64 + lane];
            h1 = g_h1[n * 64 + 32 + lane];
        }
        sH[i * 64 + lane] = h0;
        sH[i * 64 + 32 + lane] = h1;
    }
    __syncwarp();

    ull bias_p = ((const ull*)sbias)[lane];
    ull acc[8];
#pragma unroll
    for (int i = 0; i < 8; i++) acc[i] = bias_p;

    const ull* wlp = (const ull*)swl;
    const ull* wrp = (const ull*)swr;
#pragma unroll
    for (int lb = 0; lb < 16; lb++) {
        ull wl0 = wlp[(lb * 4 + 0) * 32 + lane];
        ull wl1 = wlp[(lb * 4 + 1) * 32 + lane];
        ull wl2 = wlp[(lb * 4 + 2) * 32 + lane];
        ull wl3 = wlp[(lb * 4 + 3) * 32 + lane];
        ull wr0 = wrp[(lb * 4 + 0) * 32 + lane];
        ull wr1 = wrp[(lb * 4 + 1) * 32 + lane];
        ull wr2 = wrp[(lb * 4 + 2) * 32 + lane];
        ull wr3 = wrp[(lb * 4 + 3) * 32 + lane];
#pragma unroll
        for (int i = 0; i < 8; i++) {
            float4 a4 = *(const float4*)&sA[i * 64 + lb * 4];
            float4 h4 = *(const float4*)&sH[i * 64 + lb * 4];
            acc[i] = ffma2(dup2(a4.x), wl0, acc[i]);
            acc[i] = ffma2(dup2(h4.x), wr0, acc[i]);
            acc[i] = ffma2(dup2(a4.y), wl1, acc[i]);
            acc[i] = ffma2(dup2(h4.y), wr1, acc[i]);
            acc[i] = ffma2(dup2(a4.z), wl2, acc[i]);
            acc[i] = ffma2(dup2(h4.z), wr2, acc[i]);
            acc[i] = ffma2(dup2(a4.w), wl3, acc[i]);
            acc[i] = ffma2(dup2(h4.w), wr3, acc[i]);
        }
    }

#pragma unroll
    for (int i = 0; i < 8; i++) {
        int n = n0 + i;
        if (n >= N) break;
        float2 o = unpack2(acc[i]);
        float ss = o.x * o.x + o.y * o.y;
#pragma unroll
        for (int off = 16; off > 0; off >>= 1) ss += __shfl_xor_sync(0xffffffffu, ss, off);
        float inv = 1.f / fmaxf(sqrtf(ss), 1e-12f);
        float v0 = fmaxf(o.x * inv, 0.f);
        float v1 = fmaxf(o.y * inv, 0.f);
        int b = batch[n];
        red_add_f32(&g_gsum[b * 64 + lane], v0);
        red_add_f32(&g_gsum[b * 64 + 32 + lane], v1);
        if (lane == 0) red_add_f32(&g_gcnt[b], 1.f);
    }
}

// head MLP
__global__ void head_kernel(const float* __restrict__ p1w, const float* __restrict__ p1b,
                            const float* __restrict__ p2w, const float* __restrict__ p2b,
                            const float* __restrict__ ow, const float* __restrict__ ob,
                            float* __restrict__ out) {
    int g = blockIdx.x;
    int t = threadIdx.x;
    __shared__ float sg[64];
    __shared__ float sh[64];
    __shared__ float s2[16];

    float c = g_gcnt[g];
    float invc = 1.f / fmaxf(c, 1.f);
    sg[t] = g_gsum[g * 64 + t] * invc;
    __syncthreads();

    float acc = p1b[t];
#pragma unroll 8
    for (int k = 0; k < 64; k++) acc = fmaf(sg[k], p1w[k * 64 + t], acc);
    sh[t] = fmaxf(acc, 0.f);
    __syncthreads();

    if (t < 16) {
        float a = p2b[t];
#pragma unroll 8
        for (int k = 0; k < 64; k++) a = fmaf(sh[k], p2w[k * 16 + t], a);
        s2[t] = fmaxf(a, 0.f);
    }
    __syncthreads();

    if (t == 0) {
        float a = ob[0];
#pragma unroll
        for (int k = 0; k < 16; k++) a = fmaf(s2[k], ow[k], a);
        out[g] = a;
    }
}

// ---------------------------------------------------------------------------
extern "C" void kernel_launch(void* const* d_in, const int* in_sizes, int n_in,
                              void* d_out, int out_size) {
    const float* x = (const float*)d_in[0];
    const int* ei = (const int*)d_in[1];
    const int* batch = (const int*)d_in[2];

    int base = n_in - 14;
    const float* pre_w = (const float*)d_in[base + 0];
    const float* pre_b = (const float*)d_in[base + 1];
    const float* c1_wl = (const float*)d_in[base + 2];
    const float* c1_bl = (const float*)d_in[base + 3];
    const float* c1_wr = (const float*)d_in[base + 4];
    const float* c2_wl = (const float*)d_in[base + 5];
    const float* c2_bl = (const float*)d_in[base + 6];
    const float* c2_wr = (const float*)d_in[base + 7];
    const float* p1_w = (const float*)d_in[base + 8];
    const float* p1_b = (const float*)d_in[base + 9];
    const float* p2_w = (const float*)d_in[base + 10];
    const float* p2_b = (const float*)d_in[base + 11];
    const float* o_w = (const float*)d_in[base + 12];
    const float* o_b = (const float*)d_in[base + 13];

    int N = in_sizes[0] / 5;
    int E = in_sizes[1] / 2;
    const int* src = ei;
    const int* dst = ei + E;
    float* out = (float*)d_out;

    const int smem1 = 8192 + 8192 + 256 + 16 * 2048;
    const int smem2 = 16384 + 16384 + 256 + 16 * 4096;
    cudaFuncSetAttribute(conv1, cudaFuncAttributeMaxDynamicSharedMemorySize, smem1);
    cudaFuncSetAttribute(conv2, cudaFuncAttributeMaxDynamicSharedMemorySize, smem2);

    int nb = (N + SCAN_B - 1) / SCAN_B;

    zero_small<<<256, 256>>>(N);                         // 0
    hist_kernel<<<(E + 255) / 256, 256>>>(dst, E);       // 1
    scan_kernel<<<nb, SCAN_B>>>(N);                      // 2
    place_kernel<<<(E + 255) / 256, 256>>>(src, dst, E); // 3 (profiler window)
    pre_kernel<<<(N + 255) / 256, 256>>>(x, pre_w, pre_b, N); // 4

    conv1<<<(N + 127) / 128, 512, smem1>>>(c1_wl, c1_bl, c1_wr, N);       // 5
    conv2<<<(N + 127) / 128, 512, smem2>>>(batch, c2_wl, c2_bl, c2_wr, N); // 6

    head_kernel<<<out_size, 64>>>(p1_w, p1_b, p2_w, p2_b, o_w, o_b, out); // 7
}